// round 12
// baseline (speedup 1.0000x reference)
#include <cuda_runtime.h>
#include <math.h>

#define BB 8
#define CC 4
#define HH 192
#define WW 192
#define HW (HH*WW)
#define NP 24          // (batch, class) pairs
#define NM 48          // (pair, direction): even = pred surface, odd = gt surface
#define SENT_KEY 73727 // key for empty source surface (f = 1e9)
#define WPR 6          // u32 words per row
#define WPM 1152       // words per mask bitmap
#define CHUNK 48       // rows per chunk
#define NCH 4          // chunks

__device__ __align__(16) unsigned char d_pred[BB*HW];
__device__ unsigned d_surf[NM*WPM];   // surface bitmaps
__device__ int      d_keys[NM*HW];    // per-voxel keys at fixed positions
__device__ int      d_hist[NM*288];   // coarse histograms
__device__ int      d_max[NM];
__device__ int      d_tick[NM];
__device__ int      d_done;
__device__ float    d_res[NM*2];      // [m][0]=p95, [m][1]=p100

// ---------------------------------------------------------------- K1: argmax (softmax monotone; first-max ties) + clears
__global__ void argmax_kernel(const float* __restrict__ logits) {
    int idx = blockIdx.x*blockDim.x + threadIdx.x;
    if (idx < NM) { d_tick[idx] = 0; d_max[idx] = 0; }
    if (idx == NM) d_done = 0;
    if (idx < NM*288) d_hist[idx] = 0;
    int pix4 = idx * 4;
    if (pix4 >= BB*HW) return;
    int b = pix4 / HW;
    int p = pix4 - b*HW;
    const float* base = logits + (size_t)b*CC*HW + p;
    float4 v0 = *(const float4*)(base);
    float4 v1 = *(const float4*)(base + HW);
    float4 v2 = *(const float4*)(base + 2*HW);
    float4 v3 = *(const float4*)(base + 3*HW);
    uchar4 r;
    #define AMAX(cp, dst) { \
        float bv = v0.cp; int bi = 0; \
        if (v1.cp > bv) { bv = v1.cp; bi = 1; } \
        if (v2.cp > bv) { bv = v2.cp; bi = 2; } \
        if (v3.cp > bv) { bv = v3.cp; bi = 3; } \
        dst = (unsigned char)bi; }
    AMAX(x, r.x) AMAX(y, r.y) AMAX(z, r.z) AMAX(w, r.w)
    #undef AMAX
    *(uchar4*)(d_pred + pix4) = r;
}

// ---------------------------------------------------------------- K2: surface bitmaps (pair x row-chunk)
// target is int32 (JAX x64-disabled downcasts the reference's int64). Border = background.
__global__ void __launch_bounds__(512) surf_kernel(const int* __restrict__ target) {
    __shared__ unsigned fgP[(CHUNK+2)*WPR], fgG[(CHUNK+2)*WPR];
    int pair = blockIdx.x;
    int r0 = blockIdx.y * CHUNK;
    int b = pair / 3;
    int c = pair - b*3 + 1;
    int tid = threadIdx.x;
    unsigned crep = (unsigned)c * 0x01010101u;
    const unsigned char* pb = d_pred + b*HW;
    const int* tb = target + (size_t)b*HW;

    for (int k = tid; k < 2*(CHUNK+2)*WPR; k += 512) {
        int msel = (k >= (CHUNK+2)*WPR);
        int kk = msel ? k - (CHUNK+2)*WPR : k;
        int li = kk / WPR, w = kk - (kk/WPR)*WPR;
        int row = r0 - 1 + li;
        unsigned bits = 0;
        if (row >= 0 && row < HH) {
            int bp = row*WW + w*32;
            if (!msel) {
                uint4 a = *(const uint4*)(pb + bp);
                uint4 d = *(const uint4*)(pb + bp + 16);
                #define NIB(word, sh) { \
                    unsigned nb = ((__vcmpeq4(word, crep) & 0x01010101u) * 0x01020408u) >> 24; \
                    bits |= nb << (sh); }
                NIB(a.x, 0) NIB(a.y, 4) NIB(a.z, 8) NIB(a.w, 12)
                NIB(d.x, 16) NIB(d.y, 20) NIB(d.z, 24) NIB(d.w, 28)
                #undef NIB
            } else {
                const int4* t4 = (const int4*)(tb + bp);
                #pragma unroll
                for (int q = 0; q < 8; q++) {
                    int4 tv = t4[q];
                    bits |= ((tv.x==c)?1u:0u) << (4*q);
                    bits |= ((tv.y==c)?2u:0u) << (4*q);
                    bits |= ((tv.z==c)?4u:0u) << (4*q);
                    bits |= ((tv.w==c)?8u:0u) << (4*q);
                }
            }
        }
        (msel ? fgG : fgP)[kk] = bits;
    }
    __syncthreads();

    for (int k = tid; k < 2*CHUNK*WPR; k += 512) {
        int msel = (k >= CHUNK*WPR);
        int kk = msel ? k - CHUNK*WPR : k;
        int li = kk / WPR + 1, w = kk - (kk/WPR)*WPR;
        const unsigned* fg = msel ? fgG : fgP;
        int base = li*WPR;
        unsigned f  = fg[base + w];
        unsigned up = fg[base - WPR + w];
        unsigned dn = fg[base + WPR + w];
        unsigned lw = (w > 0) ? fg[base + w - 1] : 0u;
        unsigned nx = (w < 5) ? fg[base + w + 1] : 0u;
        unsigned lf = (f << 1) | (lw >> 31);
        unsigned rt = (f >> 1) | (nx << 31);
        int m = pair*2 + msel;
        d_surf[m*WPM + (r0 + li - 1)*WPR + w] = f & ~(up & dn & lf & rt);
    }
}

// nearest set-bit distance in a 192-bit row to column jj (row must be non-empty)
__device__ __forceinline__ int nearest_col(const unsigned* row, int jj) {
    int wq = jj >> 5, bit = jj & 31;
    int dl = 1 << 12, dr = 1 << 12;
    unsigned ml = row[wq] & (0xFFFFFFFFu >> (31 - bit));   // bits 0..bit
    if (ml) dl = jj - (wq*32 + 31 - __clz(ml));
    else for (int w = wq - 1; w >= 0; w--) {
        unsigned x = row[w];
        if (x) { dl = jj - (w*32 + 31 - __clz(x)); break; }
    }
    unsigned mr = row[wq] & (0xFFFFFFFFu << bit);          // bits bit..31
    if (mr) dr = (wq*32 + __ffs(mr) - 1) - jj;
    else for (int w = wq + 1; w < WPR; w++) {
        unsigned x = row[w];
        if (x) { dr = (w*32 + __ffs(x) - 1) - jj; break; }
    }
    return min(dl, dr);
}

// ---------------------------------------------------------------- K3: exact EDT sampling from bitmaps + fused selection
// Distance field of mask m's surface, sampled at mask (m^1)'s surface voxels.
// All candidates are exact integers (f32 min-plus on them is exact -> int min identical).
__global__ void __launch_bounds__(256) dist_kernel(float* __restrict__ out) {
    __shared__ unsigned srcS[WPM];
    __shared__ unsigned oppS[CHUNK*WPR];
    __shared__ unsigned rowAnyS[WPR];
    __shared__ int hist[288];
    __shared__ int misc[6];
    int m = blockIdx.x;
    int r0 = blockIdx.y * CHUNK;
    int tid = threadIdx.x;
    int lane = tid & 31;

    for (int k = tid; k < WPM; k += 256) srcS[k] = d_surf[m*WPM + k];
    for (int k = tid; k < CHUNK*WPR; k += 256) oppS[k] = d_surf[(m^1)*WPM + r0*WPR + k];
    for (int k = tid; k < 288; k += 256) hist[k] = 0;
    if (tid == 0) misc[0] = 0;
    __syncthreads();
    if (tid < HH) {
        bool any = false;
        #pragma unroll
        for (int w = 0; w < WPR; w++) any |= (srcS[tid*WPR + w] != 0);
        unsigned bal = __ballot_sync(0xffffffffu, any);
        if (lane == 0) rowAnyS[tid >> 5] = bal;
    }
    __syncthreads();

    int locmax = 0;
    for (int pos = tid; pos < CHUNK*WW; pos += 256) {
        int lr = pos / WW, j = pos - lr*WW;
        if ((oppS[lr*WPR + (j >> 5)] >> (j & 31)) & 1) {
            int r = r0 + lr;
            int v = 1 << 30;
            for (int dd = 0; dd < HH; dd++) {
                if (dd*dd >= v) break;                    // exact prune
                int ru = r - dd, rd = r + dd;
                if (ru >= 0 && ((rowAnyS[ru >> 5] >> (ru & 31)) & 1)) {
                    int dc = nearest_col(srcS + ru*WPR, j);
                    v = min(v, dd*dd + dc*dc);
                }
                if (dd > 0 && rd < HH && ((rowAnyS[rd >> 5] >> (rd & 31)) & 1)) {
                    int dc = nearest_col(srcS + rd*WPR, j);
                    v = min(v, dd*dd + dc*dc);
                }
            }
            int key = (v > 73000) ? SENT_KEY : v;
            d_keys[m*HW + r*WW + j] = key;
            locmax = max(locmax, key);
            int bin = key >> 8;
            unsigned am = __activemask();
            unsigned grp = __match_any_sync(am, bin);
            if ((int)(__ffs(grp) - 1) == lane) atomicAdd(&hist[bin], __popc(grp));
        }
    }
    atomicMax(&misc[0], locmax);
    __syncthreads();
    if (misc[0] > 0 && tid == 0) atomicMax(&d_max[m], misc[0]);
    for (int k = tid; k < 288; k += 256)
        if (hist[k]) atomicAdd(&d_hist[m*288 + k], hist[k]);

    // ticket: last chunk of this mask runs selection
    __threadfence();
    __syncthreads();
    if (tid == 0) {
        misc[1] = (atomicAdd(&d_tick[m], 1) == NCH - 1) ? 1 : 0;
        if (misc[1]) d_tick[m] = 0;    // reset for next replay
    }
    __syncthreads();
    if (!misc[1]) return;
    __threadfence();

    // ---- selection: n = |opposite surface|; p100 = max; p95 = rank ceil(0.95f*n)
    for (int k = tid; k < WPM; k += 256) srcS[k] = d_surf[(m^1)*WPM + k];  // reuse as opp
    if (tid == 0) misc[2] = 0;
    __syncthreads();
    {
        int pc = 0;
        for (int k = tid; k < WPM; k += 256) pc += __popc(srcS[k]);
        #pragma unroll
        for (int off = 16; off > 0; off >>= 1) pc += __shfl_down_sync(0xffffffffu, pc, off);
        if (lane == 0) atomicAdd(&misc[2], pc);
    }
    __syncthreads();
    int n = misc[2];
    if (n == 0) {
        if (tid == 0) { d_res[m*2] = INFINITY; d_res[m*2+1] = INFINITY; }
    } else {
        for (int k = tid; k < 288; k += 256) hist[k] = d_hist[m*288 + k];
        __syncthreads();
        if (tid == 0) {
            int r95 = (int)ceilf(0.95f * (float)n);       // matches jnp f32 semantics
            r95 = max(1, min(r95, n));
            int cum = 0, cb = 287;
            for (int k = 0; k < 288; k++) {
                if (cum + hist[k] >= r95) { cb = k; break; }
                cum += hist[k];
            }
            misc[3] = cb; misc[4] = r95 - cum;
        }
        __syncthreads();
        int cb = misc[3];
        for (int k = tid; k < 256; k += 256) hist[k] = 0;  // reuse as fine hist
        __syncthreads();
        const int* gkeys = d_keys + m*HW;
        for (int pos = tid; pos < HW; pos += 256) {
            if ((srcS[pos >> 5] >> (pos & 31)) & 1) {      // WPR*32=192=WW so linear bit index == pixel
                int key = gkeys[pos];
                if ((key >> 8) == cb) {
                    int fb = key & 255;
                    unsigned am = __activemask();
                    unsigned grp = __match_any_sync(am, fb);
                    if ((int)(__ffs(grp) - 1) == lane) atomicAdd(&hist[fb], __popc(grp));
                }
            }
        }
        __syncthreads();
        if (tid == 0) {
            int cum = 0, key95 = cb << 8;
            for (int k = 0; k < 256; k++) {
                cum += hist[k];
                if (cum >= misc[4]) { key95 += k; break; }
            }
            int keymax = d_max[m];
            d_res[m*2+0] = (key95  == SENT_KEY) ? sqrtf(1e9f) : sqrtf((float)key95);
            d_res[m*2+1] = (keymax == SENT_KEY) ? sqrtf(1e9f) : sqrtf((float)keymax);
        }
    }

    // ---- final reduce: last mask to finish (order-independent -> deterministic)
    __threadfence();
    __syncthreads();
    if (tid == 0 && atomicAdd(&d_done, 1) == NM - 1) {
        __threadfence();
        float s100 = 0.0f, s95 = 0.0f;
        #pragma unroll
        for (int p = 0; p < NP; p++) {
            s95  += fmaxf(d_res[(2*p)*2 + 0], d_res[(2*p+1)*2 + 0]);
            s100 += fmaxf(d_res[(2*p)*2 + 1], d_res[(2*p+1)*2 + 1]);
        }
        out[0] = s100 / (float)NP;
        out[1] = s95  / (float)NP;
        d_done = 0;   // reset for next replay
    }
}

extern "C" void kernel_launch(void* const* d_in, const int* in_sizes, int n_in,
                              void* d_out, int out_size) {
    const float* logits = (const float*)d_in[0];
    const int*   target = (const int*)d_in[1];
    float* out = (float*)d_out;

    argmax_kernel<<<(BB*HW/4 + 255)/256, 256>>>(logits);
    surf_kernel  <<<dim3(NP, NCH), 512>>>(target);
    dist_kernel  <<<dim3(NM, NCH), 256>>>(out);
}

// round 13
// speedup vs baseline: 1.8547x; 1.8547x over previous
#include <cuda_runtime.h>
#include <math.h>

#define BB 8
#define CC 4
#define HH 192
#define WW 192
#define HW (HH*WW)
#define NP 24          // (batch, class) pairs
#define NM 48          // (pair, direction)
#define SENT_KEY 73727 // key for empty source surface (f = 1e9)
#define WPR 6          // u32 words per 192-bit row/column
#define WPM 1152
#define LIST_MAX 20480

// dynamic smem layout (bytes)
#define OFF_G     0          // float [HW]        147456
#define OFF_LIST  147456     // u16 [LIST_MAX]    40960
#define OFF_FGP   188416     // u32 [1152]
#define OFF_FGG   193024     // u32 [1152]
#define OFF_SFP   197632     // u32 [1152]
#define OFF_SFG   202240     // u32 [1152]
#define OFF_COLT  206848     // u32 [1152] transposed source surface
#define OFF_ROWC  211456     // int [192]
#define OFF_ROWO  212224     // int [192]
#define OFF_HIST  212992     // int [288]
#define OFF_FINE  214144     // int [256]
#define OFF_MISC  215168     // int [8]
#define SMEM_TOTAL 215200

__device__ __align__(16) unsigned char d_pred[BB*HW];
__device__ int   d_keys[NM*HW];   // per-mask keys at deterministic offsets
__device__ float d_res[NM*2];     // [m][0]=p95, [m][1]=p100
__device__ int   d_done;

extern __shared__ char smem[];

// ---------------------------------------------------------------- K1: argmax (softmax monotone; first-max ties)
__global__ void argmax_kernel(const float* __restrict__ logits) {
    int idx = blockIdx.x*blockDim.x + threadIdx.x;
    if (idx == 0) d_done = 0;
    int pix4 = idx * 4;
    if (pix4 >= BB*HW) return;
    int b = pix4 / HW;
    int p = pix4 - b*HW;
    const float* base = logits + (size_t)b*CC*HW + p;
    float4 v0 = *(const float4*)(base);
    float4 v1 = *(const float4*)(base + HW);
    float4 v2 = *(const float4*)(base + 2*HW);
    float4 v3 = *(const float4*)(base + 3*HW);
    uchar4 r;
    #define AMAX(cp, dst) { \
        float bv = v0.cp; int bi = 0; \
        if (v1.cp > bv) { bv = v1.cp; bi = 1; } \
        if (v2.cp > bv) { bv = v2.cp; bi = 2; } \
        if (v3.cp > bv) { bv = v3.cp; bi = 3; } \
        dst = (unsigned char)bi; }
    AMAX(x, r.x) AMAX(y, r.y) AMAX(z, r.z) AMAX(w, r.w)
    #undef AMAX
    *(uchar4*)(d_pred + pix4) = r;
}

// nearest set-bit distance in a 192-bit vector to position jj (4096 if empty)
__device__ __forceinline__ int nearest_bit(const unsigned* vec, int jj) {
    int wq = jj >> 5, bit = jj & 31;
    int dl = 1 << 12, dr = 1 << 12;
    unsigned ml = vec[wq] & (0xFFFFFFFFu >> (31 - bit));
    if (ml) dl = jj - (wq*32 + 31 - __clz(ml));
    else for (int w = wq - 1; w >= 0; w--) {
        unsigned x = vec[w];
        if (x) { dl = jj - (w*32 + 31 - __clz(x)); break; }
    }
    unsigned mr = vec[wq] & (0xFFFFFFFFu << bit);
    if (mr) dr = (wq*32 + __ffs(mr) - 1) - jj;
    else for (int w = wq + 1; w < WPR; w++) {
        unsigned x = vec[w];
        if (x) { dr = (w*32 + __ffs(x) - 1) - jj; break; }
    }
    return min(dl, dr);
}

// ---------------------------------------------------------------- K2: one mask per block, fully fused
__global__ void __launch_bounds__(1024) mega_kernel(const int* __restrict__ target,
                                                    float* __restrict__ out) {
    float*          gS   = (float*)(smem + OFF_G);
    unsigned short* list = (unsigned short*)(smem + OFF_LIST);
    unsigned* fgP  = (unsigned*)(smem + OFF_FGP);
    unsigned* fgG  = (unsigned*)(smem + OFF_FGG);
    unsigned* sfP  = (unsigned*)(smem + OFF_SFP);
    unsigned* sfG  = (unsigned*)(smem + OFF_SFG);
    unsigned* colT = (unsigned*)(smem + OFF_COLT);
    int* rowc = (int*)(smem + OFF_ROWC);
    int* rowo = (int*)(smem + OFF_ROWO);
    int* hist = (int*)(smem + OFF_HIST);
    int* fine = (int*)(smem + OFF_FINE);
    int* misc = (int*)(smem + OFF_MISC);

    const int T = 1024;
    int m = blockIdx.x;
    int pairI = m >> 1;
    int b = pairI / 3;
    int c = pairI - b*3 + 1;
    int tid = threadIdx.x;
    int lane = tid & 31;
    int wid = tid >> 5;

    // ---- A: fg bitmaps from pred bytes / int32 target (word-per-thread, no atomics)
    {
        unsigned crep = (unsigned)c * 0x01010101u;
        const uint4* pb = (const uint4*)(d_pred + b*HW);
        const int4*  tb = (const int4*)(target + (size_t)b*HW);
        for (int k = tid; k < WPM; k += T) {
            unsigned wp = 0;
            uint4 pa = pb[k*2], pc = pb[k*2 + 1];
            #define NIB(word, sh) { \
                unsigned nb = ((__vcmpeq4(word, crep) & 0x01010101u) * 0x01020408u) >> 24; \
                wp |= nb << (sh); }
            NIB(pa.x, 0) NIB(pa.y, 4) NIB(pa.z, 8) NIB(pa.w, 12)
            NIB(pc.x, 16) NIB(pc.y, 20) NIB(pc.z, 24) NIB(pc.w, 28)
            #undef NIB
            fgP[k] = wp;
            unsigned wg = 0;
            #pragma unroll
            for (int q = 0; q < 8; q++) {
                int4 tv = tb[k*8 + q];
                wg |= ((tv.x==c)?1u:0u) << (4*q);
                wg |= ((tv.y==c)?2u:0u) << (4*q);
                wg |= ((tv.z==c)?4u:0u) << (4*q);
                wg |= ((tv.w==c)?8u:0u) << (4*q);
            }
            fgG[k] = wg;
        }
    }
    if (tid == 0) misc[1] = 0;
    __syncthreads();

    // ---- B: 4-neighbor surfaces via bit ops (image border = background)
    for (int idx = tid; idx < 2*WPM; idx += T) {
        const unsigned* fg = (idx < WPM) ? fgP : fgG;
        unsigned* sf = (idx < WPM) ? sfP : sfG;
        int k = (idx < WPM) ? idx : idx - WPM;
        int i = k / 6, w = k - (k/6)*6;
        unsigned f  = fg[k];
        unsigned up = (i > 0)    ? fg[k-6] : 0u;
        unsigned dn = (i < HH-1) ? fg[k+6] : 0u;
        unsigned lw = (w > 0) ? fg[k-1] : 0u;
        unsigned nx = (w < 5) ? fg[k+1] : 0u;
        unsigned lf = (f << 1) | (lw >> 31);
        unsigned rt = (f >> 1) | (nx << 31);
        sf[k] = f & ~(up & dn & lf & rt);
    }
    __syncthreads();

    const unsigned* sS = (m & 1) ? sfG : sfP;   // source surface (distance field of mask m)
    const unsigned* sO = (m & 1) ? sfP : sfG;   // opposite surface (sample points)

    // ---- T: ballot-transpose sS into column bitmaps colT (36 32x32 tiles)
    for (int tt = wid; tt < 36; tt += 32) {
        int rg = tt / 6, w = tt - (tt/6)*6;
        unsigned x = sS[(rg*32 + lane)*WPR + w];
        #pragma unroll
        for (int bb2 = 0; bb2 < 32; bb2++) {
            unsigned bal = __ballot_sync(0xffffffffu, (x >> bb2) & 1u);
            if (lane == bb2) colT[(w*32 + bb2)*WPR + rg] = bal;
        }
    }
    // ---- D1 (concurrent): per-row popcounts of the sample surface
    if (tid >= 512 && tid < 512 + HH) {
        int r = tid - 512;
        int s = 0;
        #pragma unroll
        for (int w = 0; w < 6; w++) s += __popc(sO[r*6 + w]);
        rowc[r] = s;
    }
    __syncthreads();

    // ---- C': column EDT per voxel from transposed bitmap (fully parallel, exact)
    for (int pos = tid; pos < HW; pos += T) {
        int i = pos / WW, j = pos - (pos/WW)*WW;
        int d = nearest_bit(colT + j*WPR, i);
        gS[pos] = (d >= HH) ? 1e9f : (float)(d*d);
    }

    // ---- D2: exclusive prefix over 192 row counts (warp 0)
    if (tid < 32) {
        int loc[6]; int lsum = 0;
        #pragma unroll
        for (int k = 0; k < 6; k++) { loc[k] = lsum; lsum += rowc[tid*6 + k]; }
        int x = lsum;
        #pragma unroll
        for (int off = 1; off < 32; off <<= 1) {
            int y = __shfl_up_sync(0xffffffffu, x, off);
            if (lane >= off) x += y;
        }
        int excl = x - lsum;
        #pragma unroll
        for (int k = 0; k < 6; k++) rowo[tid*6 + k] = excl + loc[k];
        if (tid == 31) misc[0] = x;   // total sample count n
    }
    __syncthreads();
    int n = misc[0];

    // ---- D3: scatter (row,col) samples at prefix offsets (no atomics)
    for (int r = wid; r < HH; r += 32) {
        int base = rowo[r];
        #pragma unroll
        for (int w = 0; w < 6; w++) {
            unsigned bits = sO[r*6 + w];
            if ((bits >> lane) & 1)
                list[base + __popc(bits & ((1u << lane) - 1u))] =
                    (unsigned short)((r << 8) | (w*32 + lane));
            base += __popc(bits);
        }
    }
    for (int k = tid; k < 288; k += T) hist[k] = 0;
    if (tid < 256) fine[tid] = 0;
    __syncthreads();

    if (n == 0) {
        if (tid == 0) { d_res[m*2] = INFINITY; d_res[m*2+1] = INFINITY; }
    } else {
        // ---- E: exact outward-pruned min-plus per sample; coarse hist + max on the fly
        int* gkeys = d_keys + m*HW;
        int locmax = 0;
        for (int s0 = 0; s0 < n; s0 += T) {
            int s = s0 + tid;
            bool act = (s < n);
            int key = 0;
            if (act) {
                int e = (int)list[s];
                int r = e >> 8, jj = e & 255;
                const float* grow = gS + r*WW;
                float v = grow[jj];
                for (int dd = 1; dd < WW; dd += 2) {
                    float d2a = (float)(dd*dd);
                    if (d2a >= v) break;                 // exact: g >= 0
                    float d2b = (float)((dd+1)*(dd+1));
                    int jl = jj - dd, jr = jj + dd;
                    float ca = (jl >= 0)     ? d2a + grow[jl]   : 3e9f;
                    float cb = (jr < WW)     ? d2a + grow[jr]   : 3e9f;
                    float cc = (jl - 1 >= 0) ? d2b + grow[jl-1] : 3e9f;
                    float cd = (jr + 1 < WW) ? d2b + grow[jr+1] : 3e9f;
                    v = fminf(fminf(v, fminf(ca, cb)), fminf(cc, cd));
                }
                key = (v > 73000.0f) ? SENT_KEY : (int)v;  // exact integer or ~1e9
                gkeys[s] = key;
                locmax = max(locmax, key);
            }
            unsigned am = __ballot_sync(0xffffffffu, act);
            if (act) {
                int bin = key >> 8;
                unsigned grp = __match_any_sync(am, bin);
                if ((int)(__ffs(grp) - 1) == lane) atomicAdd(&hist[bin], __popc(grp));
            }
        }
        atomicMax(&misc[1], locmax);
        __syncthreads();

        // ---- F: p95 = rank ceil(0.95f*n) via coarse+fine; p100 = max
        if (tid == 0) {
            int r95 = (int)ceilf(0.95f * (float)n);      // matches jnp f32 semantics
            r95 = max(1, min(r95, n));
            int cum = 0, cb = 287;
            for (int k = 0; k < 288; k++) {
                if (cum + hist[k] >= r95) { cb = k; break; }
                cum += hist[k];
            }
            misc[2] = cb; misc[3] = r95 - cum;
        }
        __syncthreads();
        int cbv = misc[2];
        for (int s = tid; s < n; s += T) {
            int key = gkeys[s];
            bool hit = ((key >> 8) == cbv);
            unsigned am = __activemask();
            unsigned hm = __ballot_sync(am, hit);
            if (hit) {
                int fb = key & 255;
                unsigned grp = __match_any_sync(hm, fb);
                if ((int)(__ffs(grp) - 1) == lane) atomicAdd(&fine[fb], __popc(grp));
            }
        }
        __syncthreads();
        if (tid == 0) {
            int cum = 0, key95 = cbv << 8;
            for (int k = 0; k < 256; k++) {
                cum += fine[k];
                if (cum >= misc[3]) { key95 += k; break; }
            }
            int keymax = misc[1];
            d_res[m*2+0] = (key95  == SENT_KEY) ? sqrtf(1e9f) : sqrtf((float)key95);
            d_res[m*2+1] = (keymax == SENT_KEY) ? sqrtf(1e9f) : sqrtf((float)keymax);
        }
    }

    // ---- G: final reduce by last mask to finish (order-independent -> deterministic)
    __threadfence();
    __syncthreads();
    if (tid == 0 && atomicAdd(&d_done, 1) == NM - 1) {
        __threadfence();
        float s100 = 0.0f, s95 = 0.0f;
        #pragma unroll
        for (int p = 0; p < NP; p++) {
            s95  += fmaxf(d_res[(2*p)*2 + 0], d_res[(2*p+1)*2 + 0]);
            s100 += fmaxf(d_res[(2*p)*2 + 1], d_res[(2*p+1)*2 + 1]);
        }
        out[0] = s100 / (float)NP;
        out[1] = s95  / (float)NP;
        d_done = 0;   // reset for next replay
    }
}

extern "C" void kernel_launch(void* const* d_in, const int* in_sizes, int n_in,
                              void* d_out, int out_size) {
    const float* logits = (const float*)d_in[0];
    const int*   target = (const int*)d_in[1];
    float* out = (float*)d_out;

    cudaFuncSetAttribute(mega_kernel, cudaFuncAttributeMaxDynamicSharedMemorySize, SMEM_TOTAL);
    argmax_kernel<<<(BB*HW/4 + 255)/256, 256>>>(logits);
    mega_kernel<<<NM, 1024, SMEM_TOTAL>>>(target, out);
}

// round 14
// speedup vs baseline: 3.1853x; 1.7174x over previous
#include <cuda_runtime.h>
#include <math.h>

#define BB 8
#define CC 4
#define HH 192
#define WW 192
#define HW (HH*WW)
#define NP 24          // (batch, class) pairs
#define NM 48          // (pair, direction)
#define SENT_KEY 73727 // key for empty source surface (f = 1e9)
#define WPM 1152       // u32 words per mask bitmap
#define NSEG 4
#define SEGR 48
#define LIST_MAX 20480

// dynamic smem layout (bytes)
#define OFF_G     0        // u16 [HW]      73728  (temp: up-local; final: d^2, 65535=inf)
#define OFF_DN    73728    // u8  [HW]      36864  (down-local scan)
#define OFF_LIST  110592   // u16 [LIST_MAX] 40960
#define OFF_FGP   151552   // u32 [1152]
#define OFF_FGG   156160   // u32 [1152]
#define OFF_SFP   160768   // u32 [1152]
#define OFF_SFG   165376   // u32 [1152]
#define OFF_ROWC  169984   // int [192]
#define OFF_ROWO  170752   // int [192]
#define OFF_HIST  171520   // int [288]
#define OFF_FINE  172672   // int [256]
#define OFF_OUTD  173696   // u16 [NSEG*192]
#define OFF_OUTU  175232   // u16 [NSEG*192]
#define OFF_INCD  176768   // u16 [NSEG*192]
#define OFF_INCU  178304   // u16 [NSEG*192]
#define OFF_MISC  179840   // int [8]
#define SMEM_TOTAL 179872

__device__ __align__(16) unsigned char d_pred[BB*HW];
__device__ int   d_keys[NM*HW];
__device__ float d_res[NM*2];     // [m][0]=p95, [m][1]=p100
__device__ int   d_done;

extern __shared__ char smem[];

// ---------------------------------------------------------------- K1: argmax (softmax monotone; first-max ties)
__global__ void argmax_kernel(const float* __restrict__ logits) {
    int idx = blockIdx.x*blockDim.x + threadIdx.x;
    if (idx == 0) d_done = 0;
    int pix4 = idx * 4;
    if (pix4 >= BB*HW) return;
    int b = pix4 / HW;
    int p = pix4 - b*HW;
    const float* base = logits + (size_t)b*CC*HW + p;
    float4 v0 = *(const float4*)(base);
    float4 v1 = *(const float4*)(base + HW);
    float4 v2 = *(const float4*)(base + 2*HW);
    float4 v3 = *(const float4*)(base + 3*HW);
    uchar4 r;
    #define AMAX(cp, dst) { \
        float bv = v0.cp; int bi = 0; \
        if (v1.cp > bv) { bv = v1.cp; bi = 1; } \
        if (v2.cp > bv) { bv = v2.cp; bi = 2; } \
        if (v3.cp > bv) { bv = v3.cp; bi = 3; } \
        dst = (unsigned char)bi; }
    AMAX(x, r.x) AMAX(y, r.y) AMAX(z, r.z) AMAX(w, r.w)
    #undef AMAX
    *(uchar4*)(d_pred + pix4) = r;
}

// ---------------------------------------------------------------- K2: one mask per block, fully fused
__global__ void __launch_bounds__(1024) mega_kernel(const int* __restrict__ target,
                                                    float* __restrict__ out) {
    unsigned short* gS  = (unsigned short*)(smem + OFF_G);
    unsigned char*  dnS = (unsigned char*)(smem + OFF_DN);
    unsigned short* list = (unsigned short*)(smem + OFF_LIST);
    unsigned* fgP = (unsigned*)(smem + OFF_FGP);
    unsigned* fgG = (unsigned*)(smem + OFF_FGG);
    unsigned* sfP = (unsigned*)(smem + OFF_SFP);
    unsigned* sfG = (unsigned*)(smem + OFF_SFG);
    int* rowc = (int*)(smem + OFF_ROWC);
    int* rowo = (int*)(smem + OFF_ROWO);
    int* hist = (int*)(smem + OFF_HIST);
    int* fine = (int*)(smem + OFF_FINE);
    unsigned short* outd = (unsigned short*)(smem + OFF_OUTD);
    unsigned short* outu = (unsigned short*)(smem + OFF_OUTU);
    unsigned short* incd = (unsigned short*)(smem + OFF_INCD);
    unsigned short* incu = (unsigned short*)(smem + OFF_INCU);
    int* misc = (int*)(smem + OFF_MISC);

    const int T = 1024;
    int m = blockIdx.x;
    int pairI = m >> 1;
    int b = pairI / 3;
    int c = pairI - b*3 + 1;
    int tid = threadIdx.x;
    int lane = tid & 31;
    int wid = tid >> 5;

    // ---- A: fg bitmaps from pred bytes / int32 target (word-per-thread, no atomics)
    // target is int32 (JAX x64-disabled downcasts the reference's int64)
    {
        unsigned crep = (unsigned)c * 0x01010101u;
        const uint4* pb = (const uint4*)(d_pred + b*HW);
        const int4*  tb = (const int4*)(target + (size_t)b*HW);
        for (int k = tid; k < WPM; k += T) {
            unsigned wp = 0;
            uint4 pa = pb[k*2], pc = pb[k*2 + 1];
            #define NIB(word, sh) { \
                unsigned nb = ((__vcmpeq4(word, crep) & 0x01010101u) * 0x01020408u) >> 24; \
                wp |= nb << (sh); }
            NIB(pa.x, 0) NIB(pa.y, 4) NIB(pa.z, 8) NIB(pa.w, 12)
            NIB(pc.x, 16) NIB(pc.y, 20) NIB(pc.z, 24) NIB(pc.w, 28)
            #undef NIB
            fgP[k] = wp;
            unsigned wg = 0;
            #pragma unroll
            for (int q = 0; q < 8; q++) {
                int4 tv = tb[k*8 + q];
                wg |= ((tv.x==c)?1u:0u) << (4*q);
                wg |= ((tv.y==c)?2u:0u) << (4*q);
                wg |= ((tv.z==c)?4u:0u) << (4*q);
                wg |= ((tv.w==c)?8u:0u) << (4*q);
            }
            fgG[k] = wg;
        }
    }
    if (tid == 0) misc[1] = 0;
    __syncthreads();

    // ---- B: 4-neighbor surfaces via bit ops (image border = background)
    for (int idx = tid; idx < 2*WPM; idx += T) {
        const unsigned* fg = (idx < WPM) ? fgP : fgG;
        unsigned* sf = (idx < WPM) ? sfP : sfG;
        int k = (idx < WPM) ? idx : idx - WPM;
        int i = k / 6, w = k - (k/6)*6;
        unsigned f  = fg[k];
        unsigned up = (i > 0)    ? fg[k-6] : 0u;
        unsigned dn = (i < HH-1) ? fg[k+6] : 0u;
        unsigned lw = (w > 0) ? fg[k-1] : 0u;
        unsigned nx = (w < 5) ? fg[k+1] : 0u;
        unsigned lf = (f << 1) | (lw >> 31);
        unsigned rt = (f >> 1) | (nx << 31);
        sf[k] = f & ~(up & dn & lf & rt);
    }
    __syncthreads();

    const unsigned* sS = (m & 1) ? sfG : sfP;   // source surface (distance field of mask m)
    const unsigned* sO = (m & 1) ? sfP : sfG;   // opposite surface (sample points)

    // ---- C1 (threads 0-767): segmented local column scans (48 serial iters each)
    //      D1 (threads 768-959, concurrent): per-row popcounts of the sample surface
    if (tid < NSEG*WW) {
        int j = tid % WW, s = tid / WW;
        int r0 = s*SEGR;
        int ws = j >> 5; unsigned bm = 1u << (j & 31);
        int cnt = 255;
        #pragma unroll 8
        for (int k = 0; k < SEGR; k++) {
            bool sv = (sS[(r0 + k)*6 + ws] & bm) != 0;
            cnt = sv ? 0 : min(cnt + 1, 255);
            dnS[(r0 + k)*WW + j] = (unsigned char)cnt;
        }
        outd[s*WW + j] = (unsigned short)cnt;
        cnt = 255;
        #pragma unroll 8
        for (int k = SEGR - 1; k >= 0; k--) {
            bool sv = (sS[(r0 + k)*6 + ws] & bm) != 0;
            cnt = sv ? 0 : min(cnt + 1, 255);
            gS[(r0 + k)*WW + j] = (unsigned short)cnt;
        }
        outu[s*WW + j] = (unsigned short)cnt;
    } else if (tid < NSEG*WW + HH) {
        int r = tid - NSEG*WW;
        int s = 0;
        #pragma unroll
        for (int w = 0; w < 6; w++) s += __popc(sO[r*6 + w]);
        rowc[r] = s;
    }
    __syncthreads();

    // ---- C2 (threads 0-191): per-column incoming distances across segments
    if (tid < WW) {
        int j = tid;
        int a = 255;
        incd[0*WW + j] = 255;
        #pragma unroll
        for (int s = 1; s < NSEG; s++) {
            a = min(255, min((int)outd[(s-1)*WW + j], a + SEGR));
            incd[s*WW + j] = (unsigned short)a;
        }
        a = 255;
        incu[(NSEG-1)*WW + j] = 255;
        #pragma unroll
        for (int s = NSEG - 2; s >= 0; s--) {
            a = min(255, min((int)outu[(s+1)*WW + j], a + SEGR));
            incu[s*WW + j] = (unsigned short)a;
        }
    }
    // ---- D2 (warp 16, concurrent): exclusive prefix over 192 row counts
    if (wid == 16) {
        int loc[6]; int lsum = 0;
        #pragma unroll
        for (int k = 0; k < 6; k++) { loc[k] = lsum; lsum += rowc[lane*6 + k]; }
        int x = lsum;
        #pragma unroll
        for (int off = 1; off < 32; off <<= 1) {
            int y = __shfl_up_sync(0xffffffffu, x, off);
            if (lane >= off) x += y;
        }
        int excl = x - lsum;
        #pragma unroll
        for (int k = 0; k < 6; k++) rowo[lane*6 + k] = excl + loc[k];
        if (lane == 31) misc[0] = x;   // total sample count n
    }
    __syncthreads();

    // ---- C3: fully parallel merge -> final g (u16 squared distance; 65535 = inf)
    for (int pos = tid; pos < HW; pos += T) {
        int i = pos / WW, j = pos - (pos/WW)*WW;
        int s = i / SEGR, il = i - s*SEGR;
        int dglob = min((int)dnS[pos], min(255, (int)incd[s*WW + j] + il + 1));
        int uglob = min((int)gS[pos],  min(255, (int)incu[s*WW + j] + (SEGR - il)));
        int d = min(dglob, uglob);
        gS[pos] = (d >= HH) ? (unsigned short)65535 : (unsigned short)(d*d);
    }
    int n = misc[0];

    // ---- D3: scatter (row,col) samples at prefix offsets (no atomics)
    for (int r = wid; r < HH; r += 32) {
        int base = rowo[r];
        #pragma unroll
        for (int w = 0; w < 6; w++) {
            unsigned bits = sO[r*6 + w];
            if ((bits >> lane) & 1)
                list[base + __popc(bits & ((1u << lane) - 1u))] =
                    (unsigned short)((r << 8) | (w*32 + lane));
            base += __popc(bits);
        }
    }
    for (int k = tid; k < 288; k += T) hist[k] = 0;
    if (tid < 256) fine[tid] = 0;
    __syncthreads();

    if (n == 0) {
        if (tid == 0) { d_res[m*2] = INFINITY; d_res[m*2+1] = INFINITY; }
    } else {
        // ---- E: exact outward-pruned min-plus per sample (u16 g; conversions exact)
        int* gkeys = d_keys + m*HW;
        int locmax = 0;
        for (int s0 = 0; s0 < n; s0 += T) {
            int s = s0 + tid;
            bool act = (s < n);
            int key = 0;
            if (act) {
                int e = (int)list[s];
                int r = e >> 8, jj = e & 255;
                const unsigned short* grow = gS + r*WW;
                unsigned short raw = grow[jj];
                float v = (raw == 65535) ? 1e9f : (float)raw;
                for (int dd = 1; dd < WW; dd += 2) {
                    float d2a = (float)(dd*dd);
                    if (d2a >= v) break;                 // exact: g >= 0
                    float d2b = (float)((dd+1)*(dd+1));
                    int jl = jj - dd, jr = jj + dd;
                    float ca = 3e9f, cb = 3e9f, cc = 3e9f, cd = 3e9f;
                    unsigned short u;
                    if (jl >= 0)     { u = grow[jl];   ca = d2a + ((u==65535)?1e9f:(float)u); }
                    if (jr < WW)     { u = grow[jr];   cb = d2a + ((u==65535)?1e9f:(float)u); }
                    if (jl - 1 >= 0) { u = grow[jl-1]; cc = d2b + ((u==65535)?1e9f:(float)u); }
                    if (jr + 1 < WW) { u = grow[jr+1]; cd = d2b + ((u==65535)?1e9f:(float)u); }
                    v = fminf(fminf(v, fminf(ca, cb)), fminf(cc, cd));
                }
                key = (v > 73000.0f) ? SENT_KEY : (int)v;  // exact integer or ~1e9
                gkeys[s] = key;
                locmax = max(locmax, key);
            }
            unsigned am = __ballot_sync(0xffffffffu, act);
            if (act) {
                int bin = key >> 8;
                unsigned grp = __match_any_sync(am, bin);
                if ((int)(__ffs(grp) - 1) == lane) atomicAdd(&hist[bin], __popc(grp));
            }
        }
        atomicMax(&misc[1], locmax);
        __syncthreads();

        // ---- F: p95 = rank ceil(0.95f*n) via coarse+fine; p100 = max
        if (tid == 0) {
            int r95 = (int)ceilf(0.95f * (float)n);      // matches jnp f32 semantics
            r95 = max(1, min(r95, n));
            int cum = 0, cb = 287;
            for (int k = 0; k < 288; k++) {
                if (cum + hist[k] >= r95) { cb = k; break; }
                cum += hist[k];
            }
            misc[2] = cb; misc[3] = r95 - cum;
        }
        __syncthreads();
        int cbv = misc[2];
        for (int s = tid; s < n; s += T) {
            int key = gkeys[s];
            bool hit = ((key >> 8) == cbv);
            unsigned am = __activemask();
            unsigned hm = __ballot_sync(am, hit);
            if (hit) {
                int fb = key & 255;
                unsigned grp = __match_any_sync(hm, fb);
                if ((int)(__ffs(grp) - 1) == lane) atomicAdd(&fine[fb], __popc(grp));
            }
        }
        __syncthreads();
        if (tid == 0) {
            int cum = 0, key95 = cbv << 8;
            for (int k = 0; k < 256; k++) {
                cum += fine[k];
                if (cum >= misc[3]) { key95 += k; break; }
            }
            int keymax = misc[1];
            d_res[m*2+0] = (key95  == SENT_KEY) ? sqrtf(1e9f) : sqrtf((float)key95);
            d_res[m*2+1] = (keymax == SENT_KEY) ? sqrtf(1e9f) : sqrtf((float)keymax);
        }
    }

    // ---- G: final reduce by last mask to finish (order-independent -> deterministic)
    __threadfence();
    __syncthreads();
    if (tid == 0 && atomicAdd(&d_done, 1) == NM - 1) {
        __threadfence();
        float s100 = 0.0f, s95 = 0.0f;
        #pragma unroll
        for (int p = 0; p < NP; p++) {
            s95  += fmaxf(d_res[(2*p)*2 + 0], d_res[(2*p+1)*2 + 0]);
            s100 += fmaxf(d_res[(2*p)*2 + 1], d_res[(2*p+1)*2 + 1]);
        }
        out[0] = s100 / (float)NP;
        out[1] = s95  / (float)NP;
        d_done = 0;   // reset for next replay
    }
}

extern "C" void kernel_launch(void* const* d_in, const int* in_sizes, int n_in,
                              void* d_out, int out_size) {
    const float* logits = (const float*)d_in[0];
    const int*   target = (const int*)d_in[1];
    float* out = (float*)d_out;

    cudaFuncSetAttribute(mega_kernel, cudaFuncAttributeMaxDynamicSharedMemorySize, SMEM_TOTAL);
    argmax_kernel<<<(BB*HW/4 + 255)/256, 256>>>(logits);
    mega_kernel<<<NM, 1024, SMEM_TOTAL>>>(target, out);
}